// round 5
// baseline (speedup 1.0000x reference)
#include <cuda_runtime.h>

// Problem constants
#define K_CODES 1024
#define DIM     64
#define N_VEC   131072          // 32*64*64 spatial vectors
#define N_ELEMS 8388608         // 32*64*64*64 output tensor elements
#define HW      4096            // H*W (stride between channel planes)
#define CHUNK   128             // codes per smem chunk
#define N_CHUNKS (K_CODES / CHUNK)
#define TPB     128
#define VPB     256             // vectors per block (2 per thread)
#define NBLK    (N_VEC / VPB)   // 512

__device__ float  g_Bk[K_CODES];
__device__ double g_part[NBLK];

// ---- f32x2 packed helpers (Blackwell; only reachable via inline PTX) ----
__device__ __forceinline__ unsigned long long pack2(float lo, float hi) {
    unsigned long long r;
    asm("mov.b64 %0, {%1, %2};" : "=l"(r) : "f"(lo), "f"(hi));
    return r;
}
__device__ __forceinline__ void unpack2(unsigned long long v, float& lo, float& hi) {
    asm("mov.b64 {%0, %1}, %2;" : "=f"(lo), "=f"(hi) : "l"(v));
}
__device__ __forceinline__ unsigned long long ffma2(unsigned long long a,
                                                    unsigned long long b,
                                                    unsigned long long c) {
    unsigned long long d;
    asm("fma.rn.f32x2 %0, %1, %2, %3;" : "=l"(d) : "l"(a), "l"(b), "l"(c));
    return d;
}

// ---- Bk = sum_d e[k][d]^2, sequential fp32 (square then add, no contraction) ----
__global__ void vq_prep(const float* __restrict__ emb) {
    const int k = threadIdx.x;
    const float* row = emb + k * DIM;
    float acc = 0.0f;
#pragma unroll
    for (int d = 0; d < DIM; ++d)
        acc = __fadd_rn(acc, __fmul_rn(row[d], row[d]));
    g_Bk[k] = acc;
}

// ---- main: per-vector argmin over 1024 codes + straight-through output + loss partials ----
__global__ void __launch_bounds__(TPB) vq_main(const float* __restrict__ lat,
                                               const float* __restrict__ emb,
                                               float* __restrict__ out) {
    __shared__ float  se[CHUNK * DIM];   // 32 KB embedding chunk
    __shared__ float  sB[CHUNK];
    __shared__ double sred[TPB];

    const int t  = threadIdx.x;
    const int n0 = blockIdx.x * VPB + t;
    const int n1 = n0 + TPB;

    const int base0 = (n0 >> 12) * (DIM * HW) + (n0 & (HW - 1));
    const int base1 = (n1 >> 12) * (DIM * HW) + (n1 & (HW - 1));

    // Load x for both vectors: pack into f32x2 regs; A = sequential fp32 sum of squares
    unsigned long long xp0[DIM / 2], xp1[DIM / 2];
    float A0 = 0.0f, A1 = 0.0f;
#pragma unroll
    for (int i = 0; i < DIM / 2; ++i) {
        float a = lat[base0 + (2 * i) * HW];
        float b = lat[base0 + (2 * i + 1) * HW];
        A0 = __fadd_rn(A0, __fmul_rn(a, a));
        A0 = __fadd_rn(A0, __fmul_rn(b, b));
        xp0[i] = pack2(a, b);
        float c = lat[base1 + (2 * i) * HW];
        float d = lat[base1 + (2 * i + 1) * HW];
        A1 = __fadd_rn(A1, __fmul_rn(c, c));
        A1 = __fadd_rn(A1, __fmul_rn(d, d));
        xp1[i] = pack2(c, d);
    }

    float best0 = 3.4e38f, best1 = 3.4e38f;
    int   bi0 = 0, bi1 = 0;

    for (int kc = 0; kc < N_CHUNKS; ++kc) {
        __syncthreads();   // previous chunk fully consumed
        // cooperative chunk load: 128 codes * 64 floats
        {
            const float4* src = (const float4*)(emb + kc * CHUNK * DIM);
            float4* dst = (float4*)se;
#pragma unroll
            for (int j = 0; j < (CHUNK * DIM / 4) / TPB; ++j)
                dst[t + j * TPB] = src[t + j * TPB];
            sB[t] = g_Bk[kc * CHUNK + t];
        }
        __syncthreads();

#pragma unroll 1
        for (int kk = 0; kk < CHUNK; ++kk) {
            const unsigned long long* ep =
                (const unsigned long long*)(se + kk * DIM);
            unsigned long long a00 = 0ull, a01 = 0ull, a10 = 0ull, a11 = 0ull;
#pragma unroll
            for (int j = 0; j < DIM / 2; j += 2) {
                unsigned long long e0 = ep[j];
                unsigned long long e1 = ep[j + 1];
                a00 = ffma2(xp0[j],     e0, a00);
                a01 = ffma2(xp0[j + 1], e1, a01);
                a10 = ffma2(xp1[j],     e0, a10);
                a11 = ffma2(xp1[j + 1], e1, a11);
            }
            float l0, h0, l1, h1;
            unpack2(a00, l0, h0); unpack2(a01, l1, h1);
            const float c0 = __fadd_rn(__fadd_rn(l0, h0), __fadd_rn(l1, h1));
            unpack2(a10, l0, h0); unpack2(a11, l1, h1);
            const float c1 = __fadd_rn(__fadd_rn(l0, h0), __fadd_rn(l1, h1));

            const int   k  = kc * CHUNK + kk;
            const float bk = sB[kk];
            // dist = fl(fl(A + Bk) - fl(2*C))   (2*C exact)
            const float d0 = __fsub_rn(__fadd_rn(A0, bk), __fadd_rn(c0, c0));
            const float d1 = __fsub_rn(__fadd_rn(A1, bk), __fadd_rn(c1, c1));
            if (d0 < best0) { best0 = d0; bi0 = k; }   // strict <  -> first min (jnp.argmin)
            if (d1 < best1) { best1 = d1; bi1 = k; }
        }
    }

    // Epilogue: gather chosen code, straight-through output, loss partial.
    double lsum = 0.0;
    {
        const float* q0 = emb + bi0 * DIM;
#pragma unroll
        for (int i = 0; i < DIM / 2; ++i) {
            float xa, xb; unpack2(xp0[i], xa, xb);
            const float qa = q0[2 * i], qb = q0[2 * i + 1];
            const float da = __fsub_rn(qa, xa);
            const float db = __fsub_rn(qb, xb);
            out[base0 + (2 * i) * HW]     = __fadd_rn(xa, da);
            out[base0 + (2 * i + 1) * HW] = __fadd_rn(xb, db);
            lsum += (double)__fmul_rn(da, da);
            lsum += (double)__fmul_rn(db, db);
        }
        const float* q1 = emb + bi1 * DIM;
#pragma unroll
        for (int i = 0; i < DIM / 2; ++i) {
            float xa, xb; unpack2(xp1[i], xa, xb);
            const float qa = q1[2 * i], qb = q1[2 * i + 1];
            const float da = __fsub_rn(qa, xa);
            const float db = __fsub_rn(qb, xb);
            out[base1 + (2 * i) * HW]     = __fadd_rn(xa, da);
            out[base1 + (2 * i + 1) * HW] = __fadd_rn(xb, db);
            lsum += (double)__fmul_rn(da, da);
            lsum += (double)__fmul_rn(db, db);
        }
    }

    // deterministic fixed-order block tree reduction (no atomics)
    sred[t] = lsum;
    __syncthreads();
#pragma unroll
    for (int s = TPB / 2; s > 0; s >>= 1) {
        if (t < s) sred[t] += sred[t + s];
        __syncthreads();
    }
    if (t == 0) g_part[blockIdx.x] = sred[0];
}

// ---- finalize: deterministic sum of block partials -> vq_loss ----
__global__ void vq_fin(float* __restrict__ out, int out_size) {
    const int t = threadIdx.x;  // 32 threads
    double s = 0.0;
    const int per = NBLK / 32;
#pragma unroll 1
    for (int i = 0; i < per; ++i) s += g_part[t * per + i];
#pragma unroll
    for (int off = 16; off > 0; off >>= 1)
        s += __shfl_down_sync(0xffffffffu, s, off);
    if (t == 0) {
        const double m  = s / (double)N_ELEMS;
        const float  mf = (float)m;
        // vq_loss = fl( fl(m*0.25) + m )   (commitment*BETA + embedding, identical forward values)
        const float loss = __fadd_rn(__fmul_rn(mf, 0.25f), mf);
        for (int i = N_ELEMS; i < out_size; ++i) out[i] = loss;
    }
}

extern "C" void kernel_launch(void* const* d_in, const int* in_sizes, int n_in,
                              void* d_out, int out_size) {
    const float* lat = (const float*)d_in[0];
    const float* emb = (const float*)d_in[1];
    // robustness: metadata order should be (latents, embedding); swap if sizes say otherwise
    if (n_in >= 2 && in_sizes[0] == K_CODES * DIM && in_sizes[1] == N_ELEMS) {
        const float* tmp = lat; lat = emb; emb = tmp;
    }
    float* out = (float*)d_out;

    vq_prep<<<1, K_CODES>>>(emb);
    vq_main<<<NBLK, TPB>>>(lat, emb, out);
    vq_fin<<<1, 32>>>(out, out_size);
}

// round 6
// speedup vs baseline: 1.0606x; 1.0606x over previous
#include <cuda_runtime.h>

// Problem constants
#define K_CODES 1024
#define DIM     64
#define N_VEC   131072          // 32*64*64 spatial vectors
#define N_ELEMS 8388608         // 32*64*64*64 output tensor elements
#define HW      4096            // H*W (stride between channel planes)
#define CHUNK   128             // codes per smem chunk
#define N_CHUNKS (K_CODES / CHUNK)
#define TPB     128
#define VPB     256             // vectors per block (2 per thread)
#define NBLK    (N_VEC / VPB)   // 512

typedef unsigned long long u64;

__device__ float  g_Bk[K_CODES];
__device__ double g_part[NBLK];

// ---- f32x2 packed helpers (Blackwell; only reachable via inline PTX) ----
__device__ __forceinline__ u64 pack2(float lo, float hi) {
    u64 r;
    asm("mov.b64 %0, {%1, %2};" : "=l"(r) : "f"(lo), "f"(hi));
    return r;
}
__device__ __forceinline__ void unpack2(u64 v, float& lo, float& hi) {
    asm("mov.b64 {%0, %1}, %2;" : "=f"(lo), "=f"(hi) : "l"(v));
}
__device__ __forceinline__ u64 ffma2(u64 a, u64 b, u64 c) {
    u64 d;
    asm("fma.rn.f32x2 %0, %1, %2, %3;" : "=l"(d) : "l"(a), "l"(b), "l"(c));
    return d;
}
__device__ __forceinline__ u64 fadd2(u64 a, u64 b) {
    u64 d;
    asm("add.rn.f32x2 %0, %1, %2;" : "=l"(d) : "l"(a), "l"(b));
    return d;
}

// ---- Bk = sum_d e[k][d]^2, sequential fp32 (square then add, no contraction) ----
// Coalesced: 32 blocks x 32 threads. Stage 32 code rows into padded smem
// (stride 65 -> bank-conflict-free row walks), then per-thread sequential sum
// in EXACTLY the same order as before (bit-identical g_Bk).
__global__ void vq_prep(const float* __restrict__ emb) {
    __shared__ float s[32 * 65];
    const int t = threadIdx.x;
    const float4* src = (const float4*)(emb + blockIdx.x * 32 * DIM);
#pragma unroll
    for (int j = 0; j < 16; ++j) {
        const int g = t + j * 32;            // float4 index within 32x16 tile
        float4 v = src[g];
        const int r = g >> 4;                // code row (16 float4 per row)
        const int c = (g & 15) << 2;         // column
        float* p = s + r * 65 + c;
        p[0] = v.x; p[1] = v.y; p[2] = v.z; p[3] = v.w;
    }
    __syncthreads();
    const float* row = s + t * 65;
    float acc = 0.0f;
#pragma unroll
    for (int d = 0; d < DIM; ++d)
        acc = __fadd_rn(acc, __fmul_rn(row[d], row[d]));
    g_Bk[blockIdx.x * 32 + t] = acc;
}

// ---- main: per-vector argmin over 1024 codes + straight-through output + loss partials ----
__global__ void __launch_bounds__(TPB, 3) vq_main(const float* __restrict__ lat,
                                                  const float* __restrict__ emb,
                                                  float* __restrict__ out) {
    __shared__ float  se[CHUNK * DIM];   // 32 KB embedding chunk
    __shared__ float  sB[CHUNK];
    __shared__ double sred[TPB];

    const int t  = threadIdx.x;
    const int n0 = blockIdx.x * VPB + t;
    const int n1 = n0 + TPB;

    const int base0 = (n0 >> 12) * (DIM * HW) + (n0 & (HW - 1));
    const int base1 = (n1 >> 12) * (DIM * HW) + (n1 & (HW - 1));

    // Load x for both vectors: pack into f32x2 regs; A = sequential fp32 sum of squares
    // (identical order to the passing kernel -> bit-identical A0/A1)
    u64 xp0[DIM / 2], xp1[DIM / 2];
    float A0 = 0.0f, A1 = 0.0f;
#pragma unroll
    for (int i = 0; i < DIM / 2; ++i) {
        float a = lat[base0 + (2 * i) * HW];
        float b = lat[base0 + (2 * i + 1) * HW];
        A0 = __fadd_rn(A0, __fmul_rn(a, a));
        A0 = __fadd_rn(A0, __fmul_rn(b, b));
        xp0[i] = pack2(a, b);
        float c = lat[base1 + (2 * i) * HW];
        float d = lat[base1 + (2 * i + 1) * HW];
        A1 = __fadd_rn(A1, __fmul_rn(c, c));
        A1 = __fadd_rn(A1, __fmul_rn(d, d));
        xp1[i] = pack2(c, d);
    }
    const u64 A01  = pack2(A0, A1);
    const u64 NEG2 = pack2(-2.0f, -2.0f);

    float best0 = 3.4e38f, best1 = 3.4e38f;
    int   bi0 = 0, bi1 = 0;

    for (int kc = 0; kc < N_CHUNKS; ++kc) {
        __syncthreads();   // previous chunk fully consumed
        // cooperative chunk load: 128 codes * 64 floats
        {
            const float4* src = (const float4*)(emb + kc * CHUNK * DIM);
            float4* dst = (float4*)se;
#pragma unroll
            for (int j = 0; j < (CHUNK * DIM / 4) / TPB; ++j)
                dst[t + j * TPB] = src[t + j * TPB];
            sB[t] = g_Bk[kc * CHUNK + t];
        }
        __syncthreads();

#pragma unroll 1
        for (int kk = 0; kk < CHUNK; ++kk) {
            const float4* ep4 = (const float4*)(se + kk * DIM);
            u64 a00 = 0ull, a01 = 0ull, a10 = 0ull, a11 = 0ull;
#pragma unroll
            for (int j = 0; j < 16; j += 2) {
                float4 ea = ep4[j];
                float4 eb = ep4[j + 1];
                const u64 e0 = pack2(ea.x, ea.y);
                const u64 e1 = pack2(ea.z, ea.w);
                const u64 e2 = pack2(eb.x, eb.y);
                const u64 e3 = pack2(eb.z, eb.w);
                const int m = 2 * j;
                // identical chain mapping to the passing kernel:
                // a00/a10 take even m in ascending order, a01/a11 take odd m
                a00 = ffma2(xp0[m],     e0, a00);
                a01 = ffma2(xp0[m + 1], e1, a01);
                a00 = ffma2(xp0[m + 2], e2, a00);
                a01 = ffma2(xp0[m + 3], e3, a01);
                a10 = ffma2(xp1[m],     e0, a10);
                a11 = ffma2(xp1[m + 1], e1, a11);
                a10 = ffma2(xp1[m + 2], e2, a10);
                a11 = ffma2(xp1[m + 3], e3, a11);
            }
            // horizontal reduce: EXACT same grouping as passing kernel
            float l0, h0, l1, h1;
            unpack2(a00, l0, h0); unpack2(a01, l1, h1);
            const float c0 = __fadd_rn(__fadd_rn(l0, h0), __fadd_rn(l1, h1));
            unpack2(a10, l0, h0); unpack2(a11, l1, h1);
            const float c1 = __fadd_rn(__fadd_rn(l0, h0), __fadd_rn(l1, h1));

            const float bk = sB[kk];
            // per lane: fl(fl(A+bk) + (-2)*c) == fl(fl(A+bk) - fl(2c))  (2c exact)
            const u64 ab  = fadd2(A01, pack2(bk, bk));
            const u64 d01 = ffma2(pack2(c0, c1), NEG2, ab);
            float d0, d1; unpack2(d01, d0, d1);

            const int k = kc * CHUNK + kk;
            if (d0 < best0) { best0 = d0; bi0 = k; }   // strict < -> first min (jnp.argmin)
            if (d1 < best1) { best1 = d1; bi1 = k; }
        }
    }

    // Epilogue: gather chosen code, straight-through output, loss partial.
    double lsum = 0.0;
    {
        const float* q0 = emb + bi0 * DIM;
#pragma unroll
        for (int i = 0; i < DIM / 2; ++i) {
            float xa, xb; unpack2(xp0[i], xa, xb);
            const float qa = q0[2 * i], qb = q0[2 * i + 1];
            const float da = __fsub_rn(qa, xa);
            const float db = __fsub_rn(qb, xb);
            out[base0 + (2 * i) * HW]     = __fadd_rn(xa, da);
            out[base0 + (2 * i + 1) * HW] = __fadd_rn(xb, db);
            lsum += (double)__fmul_rn(da, da);
            lsum += (double)__fmul_rn(db, db);
        }
        const float* q1 = emb + bi1 * DIM;
#pragma unroll
        for (int i = 0; i < DIM / 2; ++i) {
            float xa, xb; unpack2(xp1[i], xa, xb);
            const float qa = q1[2 * i], qb = q1[2 * i + 1];
            const float da = __fsub_rn(qa, xa);
            const float db = __fsub_rn(qb, xb);
            out[base1 + (2 * i) * HW]     = __fadd_rn(xa, da);
            out[base1 + (2 * i + 1) * HW] = __fadd_rn(xb, db);
            lsum += (double)__fmul_rn(da, da);
            lsum += (double)__fmul_rn(db, db);
        }
    }

    // deterministic fixed-order block tree reduction (no atomics)
    sred[t] = lsum;
    __syncthreads();
#pragma unroll
    for (int s = TPB / 2; s > 0; s >>= 1) {
        if (t < s) sred[t] += sred[t + s];
        __syncthreads();
    }
    if (t == 0) g_part[blockIdx.x] = sred[0];
}

// ---- finalize: deterministic sum of block partials -> vq_loss ----
__global__ void vq_fin(float* __restrict__ out, int out_size) {
    const int t = threadIdx.x;  // 32 threads
    double s = 0.0;
    const int per = NBLK / 32;
#pragma unroll 1
    for (int i = 0; i < per; ++i) s += g_part[t * per + i];
#pragma unroll
    for (int off = 16; off > 0; off >>= 1)
        s += __shfl_down_sync(0xffffffffu, s, off);
    if (t == 0) {
        const double m  = s / (double)N_ELEMS;
        const float  mf = (float)m;
        // vq_loss = fl( fl(m*0.25) + m )   (commitment*BETA + embedding, identical forward values)
        const float loss = __fadd_rn(__fmul_rn(mf, 0.25f), mf);
        for (int i = N_ELEMS; i < out_size; ++i) out[i] = loss;
    }
}

extern "C" void kernel_launch(void* const* d_in, const int* in_sizes, int n_in,
                              void* d_out, int out_size) {
    const float* lat = (const float*)d_in[0];
    const float* emb = (const float*)d_in[1];
    // robustness: metadata order should be (latents, embedding); swap if sizes say otherwise
    if (n_in >= 2 && in_sizes[0] == K_CODES * DIM && in_sizes[1] == N_ELEMS) {
        const float* tmp = lat; lat = emb; emb = tmp;
    }
    float* out = (float*)d_out;

    vq_prep<<<K_CODES / 32, 32>>>(emb);
    vq_main<<<NBLK, TPB>>>(lat, emb, out);
    vq_fin<<<1, 32>>>(out, out_size);
}